// round 4
// baseline (speedup 1.0000x reference)
#include <cuda_runtime.h>

#define NPTS 16000
#define GPT  2000
#define CIN  128
#define COUT 128
#define DX   400
#define DY   400
#define DZ   31          // fp32: (0.9f-(-2.3f))/0.1f = 31.9999... -> 31
#define KC   62

#define HBITS 16
#define HSIZE (1 << HBITS)
#define HMASK (HSIZE - 1)
#define NCOL  (8 * DX * DY)

#define BM   32
#define KT   32
#define PCAP 256

typedef unsigned long long u64;

// ---- scratch (device globals, zero-initialized at load; cleanup restores) ----
__device__ uint2        g_tab[HSIZE];      // {key, val+1}
__device__ unsigned int g_colmask[NCOL];   // z-occupancy bits per (b,x,y)
__device__ int          g_pidx[NPTS];      // packed voxel coords
__device__ int          g_slot[NPTS];      // hash slot used by insert (or -1)

__device__ __forceinline__ unsigned int hash_key(unsigned int key) {
    return (key * 2654435761u) >> (32 - HBITS);
}

__device__ __forceinline__ u64 ffma2(u64 a, u64 b, u64 c) {
    u64 d;
    asm("fma.rn.f32x2 %0, %1, %2, %3;" : "=l"(d) : "l"(a), "l"(b), "l"(c));
    return d;
}

// ---------------------------------------------------------------------------
// Replicates: xyz = a*(hi-lo)+lo ; idx = (int)((xyz-lo)/0.1f)  (fp32, no fma)
__global__ void k_insert(const float* __restrict__ anchor) {
    int i = blockIdx.x * blockDim.x + threadIdx.x;
    if (i >= NPTS) return;

    float ax = anchor[3 * i + 0];
    float ay = anchor[3 * i + 1];
    float az = anchor[3 * i + 2];

    const float lox = -20.0f, loy = -20.0f, loz = -2.3f;
    const float step = 0.1f;

    float xx = __fadd_rn(__fmul_rn(ax, 40.0f), lox);
    float yy = __fadd_rn(__fmul_rn(ay, 40.0f), loy);
    float zz = __fadd_rn(__fmul_rn(az, __fsub_rn(0.9f, -2.3f)), loz);

    int ix = (int)__fdiv_rn(__fsub_rn(xx, lox), step);
    int iy = (int)__fdiv_rn(__fsub_rn(yy, loy), step);
    int iz = (int)__fdiv_rn(__fsub_rn(zz, loz), step);

    g_pidx[i] = (ix << 14) | (iy << 5) | iz;   // ix:9b iy:9b iz:5b

    int slot = -1;
    if (ix < DX && iy < DY && iz < DZ) {       // coords >= 0 by construction
        int b = i / GPT;
        unsigned int key = 1u + (unsigned int)((((b * DX + ix) * DY + iy) * DZ) + iz);
        unsigned int h = hash_key(key);
        while (true) {
            unsigned int old = atomicCAS(&g_tab[h].x, 0u, key);
            if (old == 0u || old == key) {
                atomicMax(&g_tab[h].y, (unsigned int)(i + 1));  // last-wins == max
                slot = (int)h;
                break;
            }
            h = (h + 1) & HMASK;
        }
        atomicOr(&g_colmask[(b * DX + ix) * DY + iy], 1u << iz);
    }
    g_slot[i] = slot;
}

// ---------------------------------------------------------------------------
__device__ __forceinline__ int hash_lookup(int b, int nx, int ny, int nz) {
    unsigned int key = 1u + (unsigned int)((((b * DX + nx) * DY + ny) * DZ) + nz);
    unsigned int h = hash_key(key);
    while (true) {
        uint2 e = g_tab[h];
        if (e.x == key) return (int)e.y - 1;
        if (e.x == 0u)  return -1;
        h = (h + 1) & HMASK;
    }
}

// ---------------------------------------------------------------------------
// Fused: per-block (32 rows) neighbor probing + gathered GEMM + rare fixups.
// smem: As dup [KT][64], Bs [KT][128], jc[32], pidx[32], pcnt, pairs[PCAP*3]
#define A_FLOATS (KT * 64)
#define B_FLOATS (KT * 128)
#define I_BASE   (A_FLOATS + B_FLOATS)
#define SMEM_FLOATS (I_BASE + 32 + 32 + 4 + PCAP * 3)

__global__ void __launch_bounds__(128, 4)
k_gemm(const float* __restrict__ feats, const float* __restrict__ w,
       float* __restrict__ out) {
    extern __shared__ float sm[];
    float* As = sm;
    float* Bs = sm + A_FLOATS;
    int* jc_s   = (int*)(sm + I_BASE);
    int* pidx_s = jc_s + 32;
    int* pcnt   = pidx_s + 32;
    int* pairs  = pcnt + 4;

    const int tid = threadIdx.x;          // 128
    const int rowbase = blockIdx.x * BM;
    const float* w62 = w + KC * CIN * COUT;

    if (tid < BM) {
        jc_s[tid] = -1;
        pidx_s[tid] = g_pidx[rowbase + tid];
    }
    if (tid == 0) *pcnt = 0;
    __syncthreads();

    // ---- probe phase: 32 rows x 25 xy-offsets (center found via own bit) ----
#pragma unroll
    for (int it = 0; it < 7; it++) {
        int q = tid + it * 128;            // 0..895 (>=800 inactive)
        int r = q & 31;
        int c = q >> 5;                    // 0..27
        if (c < 25) {
            int p  = pidx_s[r];
            int ix = p >> 14, iy = (p >> 5) & 0x1FF, iz = p & 0x1F;
            int dx = c / 5 - 2, dy = c % 5 - 2;
            int nx = ix + dx, ny = iy + dy;
            if (nx >= 0 && nx < DX && ny >= 0 && ny < DY) {
                int b = (rowbase + r) / GPT;
                unsigned int bits = g_colmask[(b * DX + nx) * DY + ny];
                int lo = iz - 2;
                unsigned int wnd = (lo >= 0) ? (0x1Fu << lo) : (0x1Fu >> -lo);
                bits &= wnd;
                while (bits) {
                    int nz = __ffs(bits) - 1;
                    bits &= bits - 1;
                    int j = hash_lookup(b, nx, ny, nz);
                    int k = (dx + 2) * 25 + (dy + 2) * 5 + (nz - iz + 2);
                    if (k == KC) {
                        jc_s[r] = j;
                    } else if (j >= 0) {
                        int pos = atomicAdd(pcnt, 1);
                        if (pos < PCAP) {
                            pairs[3 * pos + 0] = r;
                            pairs[3 * pos + 1] = k;
                            pairs[3 * pos + 2] = j;
                        }
                    }
                }
            }
        }
    }
    __syncthreads();

    // ---- main GEMM: out[rows] = feats[jc] @ w62, FFMA2 ----
    const int tx = tid & 15;               // cols 8tx..8tx+7
    const int ty = tid >> 4;               // rows 4ty..4ty+3
    u64 acc[4][4];
#pragma unroll
    for (int r = 0; r < 4; r++)
#pragma unroll
        for (int c = 0; c < 4; c++) acc[r][c] = 0ull;

    for (int k0 = 0; k0 < CIN; k0 += KT) {
        if (k0) __syncthreads();
        // fill A dup: 32 rows x 8 floats (KT=32) each -> 2 float4 per thread
#pragma unroll
        for (int it = 0; it < 2; it++) {
            int idx = tid + it * 128;       // 0..255
            int r = idx & 31, cv = idx >> 5; // cv 0..7
            int j = jc_s[r];
            float4 v = make_float4(0.f, 0.f, 0.f, 0.f);
            if (j >= 0) v = __ldg((const float4*)(feats + j * CIN + k0) + cv);
            float* d = As + (4 * cv) * 64 + 2 * r;
            *(float2*)(d + 0 * 64) = make_float2(v.x, v.x);
            *(float2*)(d + 1 * 64) = make_float2(v.y, v.y);
            *(float2*)(d + 2 * 64) = make_float2(v.z, v.z);
            *(float2*)(d + 3 * 64) = make_float2(v.w, v.w);
        }
        // fill B: 32 k x 32 float4
#pragma unroll
        for (int it = 0; it < 8; it++) {
            int idx = tid + it * 128;
            int kk = idx >> 5, cv = idx & 31;
            ((float4*)(Bs + kk * 128))[cv] =
                __ldg((const float4*)(w62 + (k0 + kk) * COUT) + cv);
        }
        __syncthreads();

#pragma unroll 4
        for (int kk = 0; kk < KT; kk++) {
            const float* Ab = As + kk * 64 + 8 * ty;
            const float* Bb = Bs + kk * 128 + 8 * tx;
            ulonglong2 a01 = *(const ulonglong2*)(Ab + 0);
            ulonglong2 a23 = *(const ulonglong2*)(Ab + 4);
            ulonglong2 b01 = *(const ulonglong2*)(Bb + 0);
            ulonglong2 b23 = *(const ulonglong2*)(Bb + 4);
            u64 ad[4] = {a01.x, a01.y, a23.x, a23.y};
            u64 bd[4] = {b01.x, b01.y, b23.x, b23.y};
#pragma unroll
            for (int r = 0; r < 4; r++)
#pragma unroll
                for (int c = 0; c < 4; c++)
                    acc[r][c] = ffma2(ad[r], bd[c], acc[r][c]);
        }
    }

#pragma unroll
    for (int r = 0; r < 4; r++) {
        int row = rowbase + 4 * ty + r;
        float2 p0 = *(float2*)&acc[r][0];
        float2 p1 = *(float2*)&acc[r][1];
        float2 p2 = *(float2*)&acc[r][2];
        float2 p3 = *(float2*)&acc[r][3];
        float4* o = (float4*)(out + row * COUT + 8 * tx);
        o[0] = make_float4(p0.x, p0.y, p1.x, p1.y);
        o[1] = make_float4(p2.x, p2.y, p3.x, p3.y);
    }
    __syncthreads();   // global stores by block visible to block

    // ---- rare non-center fixups; block owns its rows, no atomics ----
    int cnt = *pcnt;
    if (cnt > PCAP) cnt = PCAP;
    for (int p = 0; p < cnt; p++) {
        int rl = pairs[3 * p + 0];
        int kk = pairs[3 * p + 1];
        int j  = pairs[3 * p + 2];
        if (tid < COUT) {
            const float* f  = feats + j * CIN;
            const float* wk = w + kk * CIN * COUT;
            float s = 0.0f;
#pragma unroll 8
            for (int c = 0; c < CIN; c++)
                s += __ldg(f + c) * __ldg(wk + c * COUT + tid);
            out[(rowbase + rl) * COUT + tid] += s;
        }
    }
}

// ---------------------------------------------------------------------------
// restore all-zero scratch invariant for the next replay
__global__ void k_cleanup() {
    int i = blockIdx.x * blockDim.x + threadIdx.x;
    if (i >= NPTS) return;
    int slot = g_slot[i];
    if (slot >= 0) {
        g_tab[slot] = make_uint2(0u, 0u);
        int p  = g_pidx[i];
        int ix = p >> 14, iy = (p >> 5) & 0x1FF;
        int b  = i / GPT;
        g_colmask[(b * DX + ix) * DY + iy] = 0u;
    }
}

// ---------------------------------------------------------------------------
extern "C" void kernel_launch(void* const* d_in, const int* in_sizes, int n_in,
                              void* d_out, int out_size) {
    const float* feats  = (const float*)d_in[0];
    const float* anchor = (const float*)d_in[1];
    const float* w      = (const float*)d_in[2];
    float* out = (float*)d_out;

    cudaFuncSetAttribute(k_gemm, cudaFuncAttributeMaxDynamicSharedMemorySize,
                         SMEM_FLOATS * 4);

    k_insert<<<(NPTS + 255) / 256, 256>>>(anchor);
    k_gemm<<<NPTS / BM, 128, SMEM_FLOATS * 4>>>(feats, w, out);
    k_cleanup<<<(NPTS + 255) / 256, 256>>>();
}